// round 9
// baseline (speedup 1.0000x reference)
#include <cuda_runtime.h>
#include <cuda_fp16.h>
#include <cstdint>
#include <cstddef>

#define DIM      1024
#define HEADS    16
#define HEAD_DIM 64
#define BLK      32
#define FEAT     128
#define BATCH    4
#define SEQ      4096
#define NBLK     (SEQ / BLK)      // 128
#define ROWS     (BATCH * SEQ)    // 16384

// Scratch (allocation-free rule: __device__ globals)
__device__ float  g_qkv[(size_t)ROWS * 3 * DIM];     // 192 MB fp32
__device__ __half g_xh[(size_t)ROWS * DIM];
__device__ __half g_xl[(size_t)ROWS * DIM];
__device__ __half g_ah[(size_t)ROWS * DIM];
__device__ __half g_al[(size_t)ROWS * DIM];
__device__ __half g_wqh[(size_t)3 * DIM * DIM];
__device__ __half g_wql[(size_t)3 * DIM * DIM];
__device__ __half g_woh[(size_t)DIM * DIM];
__device__ __half g_wol[(size_t)DIM * DIM];

// ---------------------------------------------------------------------------
// helpers
// ---------------------------------------------------------------------------
__device__ __forceinline__ uint32_t smem_u32(const void* p) {
    uint32_t a;
    asm("{ .reg .u64 t; cvta.to.shared.u64 t, %1; cvt.u32.u64 %0, t; }" : "=r"(a) : "l"(p));
    return a;
}

#define SW128(off) ((off) ^ (((off) >> 3) & 0x70))

#define CP16(dst, src) \
    asm volatile("cp.async.cg.shared.global [%0], [%1], 16;" :: "r"(dst), "l"(src) : "memory")
#define CP_COMMIT() asm volatile("cp.async.commit_group;" ::: "memory")
#define CP_WAIT1()  asm volatile("cp.async.wait_group 1;" ::: "memory")

#define LDSM4(r0, r1, r2, r3, addr)                                           \
    asm volatile("ldmatrix.sync.aligned.m8n8.x4.shared.b16 {%0,%1,%2,%3}, [%4];" \
                 : "=r"(r0), "=r"(r1), "=r"(r2), "=r"(r3) : "r"(addr))

#define MMA_F16(d, a0, a1, a2, a3, b0, b1)                                    \
    asm volatile("mma.sync.aligned.m16n8k16.row.col.f32.f16.f16.f32 "         \
                 "{%0,%1,%2,%3}, {%4,%5,%6,%7}, {%8,%9}, {%0,%1,%2,%3};"      \
                 : "+f"((d)[0]), "+f"((d)[1]), "+f"((d)[2]), "+f"((d)[3])     \
                 : "r"(a0), "r"(a1), "r"(a2), "r"(a3), "r"(b0), "r"(b1))

// fp16x3 split: hi = rn_f16(x), lo = rn_f16(x - hi). Residual ~2^-24 |x|.
__device__ __forceinline__ void f16_split(float x, __half& hi, __half& lo) {
    hi = __float2half_rn(x);
    lo = __float2half_rn(x - __half2float(hi));
}

// ---------------------------------------------------------------------------
// fp16x3 mma.sync GEMM (unchanged from R7 best: at the HMMA issue wall).
// ---------------------------------------------------------------------------
#define BM 128
#define BN 128
#define BKH 64
#define NSTAGE 3
#define TILE_B (BM * 128)          // 16384 B per operand tile
#define ST_BYTES (4 * TILE_B)      // 65536 B (Ah, Al, Bh, Bl)
#define G_SMEM (NSTAGE * ST_BYTES) // 196608 B

template<bool BIAS>
__global__ __launch_bounds__(256)
void hgemm(const __half* __restrict__ Ah, const __half* __restrict__ Al,
           const __half* __restrict__ Bh, const __half* __restrict__ Bl,
           const float* __restrict__ bias, float* __restrict__ C,
           int M, int N, int K)
{
    extern __shared__ char smem[];
    const uint32_t sbase = smem_u32(smem);
    const int t = threadIdx.x;
    const int lid = t & 31, wid = t >> 5;
    const int wm = wid & 3, wn = wid >> 2;
    const int m0 = wm * 32, n0 = wn * 64;
    const int bn = blockIdx.x, bm = blockIdx.y;
    const int NK = K / BKH;

    const __half* Ahb = Ah + (size_t)bm * BM * K;
    const __half* Alb = Al + (size_t)bm * BM * K;
    const __half* Bhb = Bh + (size_t)bn * BN * K;
    const __half* Blb = Bl + (size_t)bn * BN * K;

    const int prow = t >> 3;
    const int pch  = t & 7;

    auto load_stage = [&](int s, int kc) {
        const uint32_t sb0 = sbase + s * ST_BYTES;
        const int koff = kc * BKH;
#pragma unroll
        for (int i = 0; i < 4; i++) {
            int row = prow + i * 32;
            uint32_t off = SW128((uint32_t)(row * 128 + pch * 16));
            size_t g = (size_t)row * K + koff + pch * 8;
            CP16(sb0 + off,              Ahb + g);
            CP16(sb0 + TILE_B + off,     Alb + g);
            CP16(sb0 + 2 * TILE_B + off, Bhb + g);
            CP16(sb0 + 3 * TILE_B + off, Blb + g);
        }
        CP_COMMIT();
    };

    const int lr = lid & 15;
    const int lk16 = (lid >> 4) * 16;
    const uint32_t aoff = (uint32_t)((m0 + lr) * 128 + lk16);
    uint32_t boff[4];
#pragma unroll
    for (int j = 0; j < 4; j++)
        boff[j] = (uint32_t)((n0 + 16 * j + lr) * 128 + lk16);

    float acc[2][8][4];
#pragma unroll
    for (int mi = 0; mi < 2; mi++)
#pragma unroll
        for (int f = 0; f < 8; f++)
#pragma unroll
            for (int r = 0; r < 4; r++) acc[mi][f][r] = 0.0f;

    load_stage(0, 0);
    load_stage(1, 1);

    for (int it = 0; it < NK; it++) {
        CP_WAIT1();
        __syncthreads();
        const int nxt = it + 2;
        if (nxt < NK) load_stage(nxt % NSTAGE, nxt);

        const uint32_t s0 = sbase + (it % NSTAGE) * ST_BYTES;
        const uint32_t sAh = s0;
        const uint32_t sAl = s0 + TILE_B;
        const uint32_t sBh = s0 + 2 * TILE_B;
        const uint32_t sBl = s0 + 3 * TILE_B;

#pragma unroll
        for (int ks = 0; ks < 4; ks++) {
            const uint32_t kb = ks * 32;
            uint32_t ah0[4], ah1[4], al0[4], al1[4];
            {
                uint32_t o0 = SW128(aoff + kb);
                uint32_t o1 = SW128(aoff + 16 * 128 + kb);
                LDSM4(ah0[0], ah0[1], ah0[2], ah0[3], sAh + o0);
                LDSM4(ah1[0], ah1[1], ah1[2], ah1[3], sAh + o1);
                LDSM4(al0[0], al0[1], al0[2], al0[3], sAl + o0);
                LDSM4(al1[0], al1[1], al1[2], al1[3], sAl + o1);
            }
#pragma unroll
            for (int j = 0; j < 4; j++) {
                uint32_t bh[4], bl[4];
                uint32_t ob = SW128(boff[j] + kb);
                LDSM4(bh[0], bh[1], bh[2], bh[3], sBh + ob);
                LDSM4(bl[0], bl[1], bl[2], bl[3], sBl + ob);

                float* d00 = acc[0][2 * j + 0];
                float* d01 = acc[0][2 * j + 1];
                float* d10 = acc[1][2 * j + 0];
                float* d11 = acc[1][2 * j + 1];

                MMA_F16(d00, ah0[0], ah0[1], ah0[2], ah0[3], bh[0], bh[2]);
                MMA_F16(d01, ah0[0], ah0[1], ah0[2], ah0[3], bh[1], bh[3]);
                MMA_F16(d10, ah1[0], ah1[1], ah1[2], ah1[3], bh[0], bh[2]);
                MMA_F16(d11, ah1[0], ah1[1], ah1[2], ah1[3], bh[1], bh[3]);
                MMA_F16(d00, al0[0], al0[1], al0[2], al0[3], bh[0], bh[2]);
                MMA_F16(d01, al0[0], al0[1], al0[2], al0[3], bh[1], bh[3]);
                MMA_F16(d10, al1[0], al1[1], al1[2], al1[3], bh[0], bh[2]);
                MMA_F16(d11, al1[0], al1[1], al1[2], al1[3], bh[1], bh[3]);
                MMA_F16(d00, ah0[0], ah0[1], ah0[2], ah0[3], bl[0], bl[2]);
                MMA_F16(d01, ah0[0], ah0[1], ah0[2], ah0[3], bl[1], bl[3]);
                MMA_F16(d10, ah1[0], ah1[1], ah1[2], ah1[3], bl[0], bl[2]);
                MMA_F16(d11, ah1[0], ah1[1], ah1[2], ah1[3], bl[1], bl[3]);
            }
        }
    }

    const int g = lid >> 2, tq = lid & 3;
#pragma unroll
    for (int mi = 0; mi < 2; mi++) {
        int rowl = m0 + mi * 16 + g;
#pragma unroll
        for (int f = 0; f < 8; f++) {
            int col = n0 + f * 8 + tq * 2;
            float b0 = 0.0f, b1 = 0.0f;
            if (BIAS) { b0 = bias[bn * BN + col]; b1 = bias[bn * BN + col + 1]; }
            float* p0 = C + (size_t)(bm * BM + rowl) * N + bn * BN + col;
            float* p1 = C + (size_t)(bm * BM + rowl + 8) * N + bn * BN + col;
            float2 v0 = { acc[mi][f][0] + b0, acc[mi][f][1] + b1 };
            float2 v1 = { acc[mi][f][2] + b0, acc[mi][f][3] + b1 };
            *(float2*)p0 = v0;
            *(float2*)p1 = v1;
        }
    }
}

// ---------------------------------------------------------------------------
// Split fp32 -> (hi, lo) fp16 arrays, elementwise (float4 vectorized).
// ---------------------------------------------------------------------------
__global__ void split_kernel(const float* __restrict__ in, __half* __restrict__ h,
                             __half* __restrict__ l, int n4)
{
    int i = blockIdx.x * blockDim.x + threadIdx.x;
    if (i >= n4) return;
    float4 v = ((const float4*)in)[i];
    __half h0, h1, h2, h3, l0, l1, l2, l3;
    f16_split(v.x, h0, l0); f16_split(v.y, h1, l1);
    f16_split(v.z, h2, l2); f16_split(v.w, h3, l3);
    ((__half2*)h)[2 * i]     = __halves2half2(h0, h1);
    ((__half2*)h)[2 * i + 1] = __halves2half2(h2, h3);
    ((__half2*)l)[2 * i]     = __halves2half2(l0, l1);
    ((__half2*)l)[2 * i + 1] = __halves2half2(l2, l3);
}

// ---------------------------------------------------------------------------
// Transpose + split: in fp32 [R,C] -> out_h/out_l fp16 [C,R]. block (32,8).
// ---------------------------------------------------------------------------
__global__ void transpose_split(const float* __restrict__ in,
                                __half* __restrict__ oh, __half* __restrict__ ol,
                                int R, int C)
{
    __shared__ float tile[32][33];
    int bx = blockIdx.x * 32, by = blockIdx.y * 32;
#pragma unroll
    for (int i = 0; i < 32; i += 8)
        tile[threadIdx.y + i][threadIdx.x] =
            in[(size_t)(by + threadIdx.y + i) * C + bx + threadIdx.x];
    __syncthreads();
#pragma unroll
    for (int i = 0; i < 32; i += 8) {
        float v = tile[threadIdx.x][threadIdx.y + i];
        __half hv, lv;
        f16_split(v, hv, lv);
        size_t idx = (size_t)(bx + threadIdx.y + i) * R + by + threadIdx.x;
        oh[idx] = hv;
        ol[idx] = lv;
    }
}

// ---------------------------------------------------------------------------
// Fused middle: per (b,h,m) 32-token block linear attention.
// Crossbar-optimized: float4 broadcast loads for q/k/qf/ksum, multicast
// float4 for kf/v, z folded into phase D (no separate z phase/sync).
// ---------------------------------------------------------------------------
#define SQF_STRIDE 132   // 16B-aligned rows; +4 skew keeps row reads clean
#define MID_Q     0
#define MID_K     2048
#define MID_V     4096
#define MID_P     6144            // proj 64x128; reused as kv[128][64]
#define MID_QF    14336           // 32 x 132
#define MID_KF    (14336 + 32 * SQF_STRIDE)
#define MID_KSUM  (MID_KF + 32 * SQF_STRIDE)
#define MID_SMEM_FLOATS (MID_KSUM + 128)
#define MID_SMEM_BYTES  (MID_SMEM_FLOATS * 4)

__global__ __launch_bounds__(256)
void middle_kernel(const float* __restrict__ qkv, const float* __restrict__ proj,
                   __half* __restrict__ attn_h, __half* __restrict__ attn_l)
{
    extern __shared__ float sm[];
    float* sq    = sm + MID_Q;
    float* sk    = sm + MID_K;
    float* sv    = sm + MID_V;
    float* sp    = sm + MID_P;
    float* skv   = sp;            // aliased after proj is dead
    float* sqf   = sm + MID_QF;
    float* skf   = sm + MID_KF;
    float* sksum = sm + MID_KSUM;

    const int t = threadIdx.x;
    const int gb = blockIdx.x;
    const int b = gb / (HEADS * NBLK);
    const int rem = gb - b * (HEADS * NBLK);
    const int h = rem / NBLK;
    const int m = rem - h * NBLK;

    // ---- phase A: stage q/k/v and proj (float4 coalesced) ----
    const float* base = qkv + ((size_t)(b * SEQ + m * BLK)) * (3 * DIM) + h * HEAD_DIM;
    for (int v4 = t; v4 < 512; v4 += 256) {
        int s = v4 >> 4, c = v4 & 15;
        const float* r = base + (size_t)s * (3 * DIM) + c * 4;
        ((float4*)sq)[v4] = *(const float4*)(r);
        ((float4*)sk)[v4] = *(const float4*)(r + DIM);
        ((float4*)sv)[v4] = *(const float4*)(r + 2 * DIM);
    }
    const float* ph = proj + (size_t)h * HEAD_DIM * FEAT;
    for (int v4 = t; v4 < 2048; v4 += 256)
        ((float4*)sp)[v4] = ((const float4*)ph)[v4];
    __syncthreads();

    // ---- phase B: qf/kf = elu(x @ proj)+1. 4x4 blocking, d unrolled x4,
    //      q/k as float4 BROADCAST loads (1 wavefront each). ----
    {
        const int tS = t >> 5;
        const int tF = t & 31;
        float qa[4][4], ka[4][4];
#pragma unroll
        for (int i = 0; i < 4; i++)
#pragma unroll
            for (int j = 0; j < 4; j++) { qa[i][j] = 0.0f; ka[i][j] = 0.0f; }

        for (int d4 = 0; d4 < HEAD_DIM; d4 += 4) {
            float4 q4[4], k4[4];
#pragma unroll
            for (int i = 0; i < 4; i++) {
                q4[i] = *(const float4*)&sq[(tS + 8 * i) * 64 + d4];
                k4[i] = *(const float4*)&sk[(tS + 8 * i) * 64 + d4];
            }
#pragma unroll
            for (int dd = 0; dd < 4; dd++) {
                float pv[4];
#pragma unroll
                for (int j = 0; j < 4; j++)
                    pv[j] = sp[(d4 + dd) * 128 + tF + 32 * j];
#pragma unroll
                for (int i = 0; i < 4; i++) {
                    float qd = (dd == 0) ? q4[i].x : (dd == 1) ? q4[i].y
                             : (dd == 2) ? q4[i].z : q4[i].w;
                    float kd = (dd == 0) ? k4[i].x : (dd == 1) ? k4[i].y
                             : (dd == 2) ? k4[i].z : k4[i].w;
#pragma unroll
                    for (int j = 0; j < 4; j++) {
                        qa[i][j] += qd * pv[j];
                        ka[i][j] += kd * pv[j];
                    }
                }
            }
        }
#pragma unroll
        for (int i = 0; i < 4; i++) {
            int s = tS + 8 * i;
#pragma unroll
            for (int j = 0; j < 4; j++) {
                int f = tF + 32 * j;
                float x = qa[i][j];
                sqf[s * SQF_STRIDE + f] = (x > 0.0f) ? (x + 1.0f) : __expf(x);
                x = ka[i][j];
                skf[s * SQF_STRIDE + f] = (x > 0.0f) ? (x + 1.0f) : __expf(x);
            }
        }
    }
    __syncthreads();

    // ---- phase C: kv[f][d] = sum_s kf[s][f]*v[s][d]; ksum = col-sums of kf.
    //      Thread tile: 4 contiguous f x 8 contiguous d -> float4 multicast. ----
    {
        const int cf = (t >> 3) * 4;   // f base (4 consecutive)
        const int cd = (t & 7) * 8;    // d base (8 consecutive)
        float kva[4][8];
#pragma unroll
        for (int j = 0; j < 4; j++)
#pragma unroll
            for (int i = 0; i < 8; i++) kva[j][i] = 0.0f;

        for (int s = 0; s < BLK; s++) {
            float4 kf4 = *(const float4*)&skf[s * SQF_STRIDE + cf];
            float4 va  = *(const float4*)&sv[s * 64 + cd];
            float4 vb  = *(const float4*)&sv[s * 64 + cd + 4];
            float vv[8] = { va.x, va.y, va.z, va.w, vb.x, vb.y, vb.z, vb.w };
            float kfv[4] = { kf4.x, kf4.y, kf4.z, kf4.w };
#pragma unroll
            for (int j = 0; j < 4; j++)
#pragma unroll
                for (int i = 0; i < 8; i++)
                    kva[j][i] += kfv[j] * vv[i];
        }
        if (t < FEAT) {
            float acc = 0.0f;
            for (int s = 0; s < BLK; s++) acc += skf[s * SQF_STRIDE + t];
            sksum[t] = acc;
        }
#pragma unroll
        for (int j = 0; j < 4; j++) {
            float4 o0 = { kva[j][0], kva[j][1], kva[j][2], kva[j][3] };
            float4 o1 = { kva[j][4], kva[j][5], kva[j][6], kva[j][7] };
            *(float4*)&skv[(cf + j) * 64 + cd]     = o0;
            *(float4*)&skv[(cf + j) * 64 + cd + 4] = o1;
        }
    }
    __syncthreads();

    // ---- phase D: out[s][d] = z[s] * sum_f qf[s][f]*kv[f][d], with
    //      z[s] = 1/(qf[s,:].ksum + eps) folded in (qf4/ks4 broadcasts). ----
    {
        const int tS = t >> 5;
        const int lane = t & 31;
        float oa[4][2];
        float zacc[4];
#pragma unroll
        for (int i = 0; i < 4; i++) { oa[i][0] = 0.0f; oa[i][1] = 0.0f; zacc[i] = 0.0f; }

        for (int f4 = 0; f4 < FEAT; f4 += 4) {
            float4 ks4 = *(const float4*)&sksum[f4];
            float4 qf4[4];
#pragma unroll
            for (int i = 0; i < 4; i++)
                qf4[i] = *(const float4*)&sqf[(tS + 8 * i) * SQF_STRIDE + f4];
#pragma unroll
            for (int i = 0; i < 4; i++)
                zacc[i] += qf4[i].x * ks4.x + qf4[i].y * ks4.y
                         + qf4[i].z * ks4.z + qf4[i].w * ks4.w;
#pragma unroll
            for (int ff = 0; ff < 4; ff++) {
                float kv0 = skv[(f4 + ff) * 64 + lane];
                float kv1 = skv[(f4 + ff) * 64 + lane + 32];
#pragma unroll
                for (int i = 0; i < 4; i++) {
                    float qv = (ff == 0) ? qf4[i].x : (ff == 1) ? qf4[i].y
                             : (ff == 2) ? qf4[i].z : qf4[i].w;
                    oa[i][0] += qv * kv0;
                    oa[i][1] += qv * kv1;
                }
            }
        }
        const int rowbase = b * SEQ + m * BLK;
#pragma unroll
        for (int i = 0; i < 4; i++) {
            int s = tS + 8 * i;
            float zz = 1.0f / (zacc[i] + 1e-8f);
            size_t off = (size_t)(rowbase + s) * DIM + h * HEAD_DIM;
            float v0 = oa[i][0] * zz;
            float v1 = oa[i][1] * zz;
            __half h0, l0, h1, l1;
            f16_split(v0, h0, l0);
            f16_split(v1, h1, l1);
            attn_h[off + lane]      = h0;
            attn_l[off + lane]      = l0;
            attn_h[off + lane + 32] = h1;
            attn_l[off + lane + 32] = l1;
        }
    }
}

// ---------------------------------------------------------------------------
extern "C" void kernel_launch(void* const* d_in, const int* in_sizes, int n_in,
                              void* d_out, int out_size)
{
    const float* x    = (const float*)d_in[0];
    const float* Wqkv = (const float*)d_in[1];
    const float* proj = (const float*)d_in[2];
    const float* Wout = (const float*)d_in[3];
    const float* bout = (const float*)d_in[4];
    float* out = (float*)d_out;

    float*  qkv; cudaGetSymbolAddress((void**)&qkv, g_qkv);
    __half *xh, *xl, *ah, *al, *wqh, *wql, *woh, *wol;
    cudaGetSymbolAddress((void**)&xh,  g_xh);
    cudaGetSymbolAddress((void**)&xl,  g_xl);
    cudaGetSymbolAddress((void**)&ah,  g_ah);
    cudaGetSymbolAddress((void**)&al,  g_al);
    cudaGetSymbolAddress((void**)&wqh, g_wqh);
    cudaGetSymbolAddress((void**)&wql, g_wql);
    cudaGetSymbolAddress((void**)&woh, g_woh);
    cudaGetSymbolAddress((void**)&wol, g_wol);

    cudaFuncSetAttribute(middle_kernel, cudaFuncAttributeMaxDynamicSharedMemorySize,
                         MID_SMEM_BYTES);
    cudaFuncSetAttribute(hgemm<false>, cudaFuncAttributeMaxDynamicSharedMemorySize,
                         G_SMEM);
    cudaFuncSetAttribute(hgemm<true>, cudaFuncAttributeMaxDynamicSharedMemorySize,
                         G_SMEM);

    // 0) operand prep: split x; transpose+split weights
    {
        int n4 = ROWS * DIM / 4;
        split_kernel<<<(n4 + 255) / 256, 256>>>(x, xh, xl, n4);
    }
    transpose_split<<<dim3((3 * DIM) / 32, DIM / 32), dim3(32, 8)>>>(Wqkv, wqh, wql, DIM, 3 * DIM);
    transpose_split<<<dim3(DIM / 32, DIM / 32), dim3(32, 8)>>>(Wout, woh, wol, DIM, DIM);

    // 1) qkv = x @ Wqkv  (fp16x3 mma.sync)
    hgemm<false><<<dim3((3 * DIM) / BN, ROWS / BM), 256, G_SMEM>>>(
        xh, xl, wqh, wql, nullptr, qkv, ROWS, 3 * DIM, DIM);

    // 2) fused per-block linear attention (writes split fp16 attn)
    middle_kernel<<<BATCH * HEADS * NBLK, 256, MID_SMEM_BYTES>>>(qkv, proj, ah, al);

    // 3) out = attn @ Wout + bout  (fp16x3 mma.sync)
    hgemm<true><<<dim3(DIM / BN, ROWS / BM), 256, G_SMEM>>>(
        ah, al, woh, wol, bout, out, ROWS, DIM, DIM);
}

// round 10
// speedup vs baseline: 1.2555x; 1.2555x over previous
#include <cuda_runtime.h>
#include <cuda_fp16.h>
#include <cstdint>
#include <cstddef>

#define DIM      1024
#define HEADS    16
#define HEAD_DIM 64
#define BLK      32
#define FEAT     128
#define BATCH    4
#define SEQ      4096
#define NBLK     (SEQ / BLK)      // 128
#define ROWS     (BATCH * SEQ)    // 16384

// Scratch (allocation-free rule: __device__ globals)
__device__ float  g_qkv[(size_t)ROWS * 3 * DIM];     // 192 MB fp32
__device__ __half g_xh[(size_t)ROWS * DIM];
__device__ __half g_xl[(size_t)ROWS * DIM];
__device__ __half g_ah[(size_t)ROWS * DIM];
__device__ __half g_al[(size_t)ROWS * DIM];
__device__ __half g_wqh[(size_t)3 * DIM * DIM];
__device__ __half g_woh[(size_t)DIM * DIM];

// ---------------------------------------------------------------------------
// helpers
// ---------------------------------------------------------------------------
__device__ __forceinline__ uint32_t smem_u32(const void* p) {
    uint32_t a;
    asm("{ .reg .u64 t; cvta.to.shared.u64 t, %1; cvt.u32.u64 %0, t; }" : "=r"(a) : "l"(p));
    return a;
}

#define SW128(off) ((off) ^ (((off) >> 3) & 0x70))

#define CP16(dst, src) \
    asm volatile("cp.async.cg.shared.global [%0], [%1], 16;" :: "r"(dst), "l"(src) : "memory")
#define CP_COMMIT() asm volatile("cp.async.commit_group;" ::: "memory")
#define CP_WAIT1()  asm volatile("cp.async.wait_group 1;" ::: "memory")

#define LDSM4(r0, r1, r2, r3, addr)                                           \
    asm volatile("ldmatrix.sync.aligned.m8n8.x4.shared.b16 {%0,%1,%2,%3}, [%4];" \
                 : "=r"(r0), "=r"(r1), "=r"(r2), "=r"(r3) : "r"(addr))

#define MMA_F16(d, a0, a1, a2, a3, b0, b1)                                    \
    asm volatile("mma.sync.aligned.m16n8k16.row.col.f32.f16.f16.f32 "         \
                 "{%0,%1,%2,%3}, {%4,%5,%6,%7}, {%8,%9}, {%0,%1,%2,%3};"      \
                 : "+f"((d)[0]), "+f"((d)[1]), "+f"((d)[2]), "+f"((d)[3])     \
                 : "r"(a0), "r"(a1), "r"(a2), "r"(a3), "r"(b0), "r"(b1))

// fp16 split: hi = rn_f16(x), lo = rn_f16(x - hi).
__device__ __forceinline__ void f16_split(float x, __half& hi, __half& lo) {
    hi = __float2half_rn(x);
    lo = __float2half_rn(x - __half2float(hi));
}

// ---------------------------------------------------------------------------
// fp16x2 mma.sync GEMM: C = A @ Bh^T (+bias); A error-compensated (hi+lo),
// B round-to-nearest fp16 (residual dropped; unbiased, ~2.8e-4 RMS rel).
// CTA 128x128, BK=64 (128B rows, SW128), 8 warps (4Mx2N), 3-stage cp.async,
// single sync/iter. Per product: Ah*Bh + Al*Bh (32 MMAs / k-step).
// ---------------------------------------------------------------------------
#define BM 128
#define BN 128
#define BKH 64
#define NSTAGE 3
#define TILE_B (BM * 128)          // 16384 B per operand tile
#define ST_BYTES (3 * TILE_B)      // 49152 B (Ah, Al, Bh)
#define G_SMEM (NSTAGE * ST_BYTES) // 147456 B

template<bool BIAS>
__global__ __launch_bounds__(256)
void hgemm(const __half* __restrict__ Ah, const __half* __restrict__ Al,
           const __half* __restrict__ Bh,
           const float* __restrict__ bias, float* __restrict__ C,
           int M, int N, int K)
{
    extern __shared__ char smem[];
    const uint32_t sbase = smem_u32(smem);
    const int t = threadIdx.x;
    const int lid = t & 31, wid = t >> 5;
    const int wm = wid & 3, wn = wid >> 2;
    const int m0 = wm * 32, n0 = wn * 64;
    const int bn = blockIdx.x, bm = blockIdx.y;
    const int NK = K / BKH;

    const __half* Ahb = Ah + (size_t)bm * BM * K;
    const __half* Alb = Al + (size_t)bm * BM * K;
    const __half* Bhb = Bh + (size_t)bn * BN * K;

    const int prow = t >> 3;
    const int pch  = t & 7;

    auto load_stage = [&](int s, int kc) {
        const uint32_t sb0 = sbase + s * ST_BYTES;
        const int koff = kc * BKH;
#pragma unroll
        for (int i = 0; i < 4; i++) {
            int row = prow + i * 32;
            uint32_t off = SW128((uint32_t)(row * 128 + pch * 16));
            size_t g = (size_t)row * K + koff + pch * 8;
            CP16(sb0 + off,              Ahb + g);
            CP16(sb0 + TILE_B + off,     Alb + g);
            CP16(sb0 + 2 * TILE_B + off, Bhb + g);
        }
        CP_COMMIT();
    };

    const int lr = lid & 15;
    const int lk16 = (lid >> 4) * 16;
    const uint32_t aoff = (uint32_t)((m0 + lr) * 128 + lk16);
    uint32_t boff[4];
#pragma unroll
    for (int j = 0; j < 4; j++)
        boff[j] = (uint32_t)((n0 + 16 * j + lr) * 128 + lk16);

    float acc[2][8][4];
#pragma unroll
    for (int mi = 0; mi < 2; mi++)
#pragma unroll
        for (int f = 0; f < 8; f++)
#pragma unroll
            for (int r = 0; r < 4; r++) acc[mi][f][r] = 0.0f;

    load_stage(0, 0);
    load_stage(1, 1);

    for (int it = 0; it < NK; it++) {
        CP_WAIT1();
        __syncthreads();
        const int nxt = it + 2;
        if (nxt < NK) load_stage(nxt % NSTAGE, nxt);

        const uint32_t s0 = sbase + (it % NSTAGE) * ST_BYTES;
        const uint32_t sAh = s0;
        const uint32_t sAl = s0 + TILE_B;
        const uint32_t sBh = s0 + 2 * TILE_B;

#pragma unroll
        for (int ks = 0; ks < 4; ks++) {
            const uint32_t kb = ks * 32;
            uint32_t ah0[4], ah1[4], al0[4], al1[4];
            {
                uint32_t o0 = SW128(aoff + kb);
                uint32_t o1 = SW128(aoff + 16 * 128 + kb);
                LDSM4(ah0[0], ah0[1], ah0[2], ah0[3], sAh + o0);
                LDSM4(ah1[0], ah1[1], ah1[2], ah1[3], sAh + o1);
                LDSM4(al0[0], al0[1], al0[2], al0[3], sAl + o0);
                LDSM4(al1[0], al1[1], al1[2], al1[3], sAl + o1);
            }
#pragma unroll
            for (int j = 0; j < 4; j++) {
                uint32_t bh[4];
                uint32_t ob = SW128(boff[j] + kb);
                LDSM4(bh[0], bh[1], bh[2], bh[3], sBh + ob);

                float* d00 = acc[0][2 * j + 0];
                float* d01 = acc[0][2 * j + 1];
                float* d10 = acc[1][2 * j + 0];
                float* d11 = acc[1][2 * j + 1];

                // hi*hi
                MMA_F16(d00, ah0[0], ah0[1], ah0[2], ah0[3], bh[0], bh[2]);
                MMA_F16(d01, ah0[0], ah0[1], ah0[2], ah0[3], bh[1], bh[3]);
                MMA_F16(d10, ah1[0], ah1[1], ah1[2], ah1[3], bh[0], bh[2]);
                MMA_F16(d11, ah1[0], ah1[1], ah1[2], ah1[3], bh[1], bh[3]);
                // lo*hi
                MMA_F16(d00, al0[0], al0[1], al0[2], al0[3], bh[0], bh[2]);
                MMA_F16(d01, al0[0], al0[1], al0[2], al0[3], bh[1], bh[3]);
                MMA_F16(d10, al1[0], al1[1], al1[2], al1[3], bh[0], bh[2]);
                MMA_F16(d11, al1[0], al1[1], al1[2], al1[3], bh[1], bh[3]);
            }
        }
    }

    const int g = lid >> 2, tq = lid & 3;
#pragma unroll
    for (int mi = 0; mi < 2; mi++) {
        int rowl = m0 + mi * 16 + g;
#pragma unroll
        for (int f = 0; f < 8; f++) {
            int col = n0 + f * 8 + tq * 2;
            float b0 = 0.0f, b1 = 0.0f;
            if (BIAS) { b0 = bias[bn * BN + col]; b1 = bias[bn * BN + col + 1]; }
            float* p0 = C + (size_t)(bm * BM + rowl) * N + bn * BN + col;
            float* p1 = C + (size_t)(bm * BM + rowl + 8) * N + bn * BN + col;
            float2 v0 = { acc[mi][f][0] + b0, acc[mi][f][1] + b1 };
            float2 v1 = { acc[mi][f][2] + b0, acc[mi][f][3] + b1 };
            *(float2*)p0 = v0;
            *(float2*)p1 = v1;
        }
    }
}

// ---------------------------------------------------------------------------
// Split fp32 -> (hi, lo) fp16 arrays, elementwise (float4 vectorized).
// ---------------------------------------------------------------------------
__global__ void split_kernel(const float* __restrict__ in, __half* __restrict__ h,
                             __half* __restrict__ l, int n4)
{
    int i = blockIdx.x * blockDim.x + threadIdx.x;
    if (i >= n4) return;
    float4 v = ((const float4*)in)[i];
    __half h0, h1, h2, h3, l0, l1, l2, l3;
    f16_split(v.x, h0, l0); f16_split(v.y, h1, l1);
    f16_split(v.z, h2, l2); f16_split(v.w, h3, l3);
    ((__half2*)h)[2 * i]     = __halves2half2(h0, h1);
    ((__half2*)h)[2 * i + 1] = __halves2half2(h2, h3);
    ((__half2*)l)[2 * i]     = __halves2half2(l0, l1);
    ((__half2*)l)[2 * i + 1] = __halves2half2(l2, l3);
}

// ---------------------------------------------------------------------------
// Transpose + round: in fp32 [R,C] -> out fp16 [C,R] (rn). block (32,8).
// ---------------------------------------------------------------------------
__global__ void transpose_h(const float* __restrict__ in,
                            __half* __restrict__ oh, int R, int C)
{
    __shared__ float tile[32][33];
    int bx = blockIdx.x * 32, by = blockIdx.y * 32;
#pragma unroll
    for (int i = 0; i < 32; i += 8)
        tile[threadIdx.y + i][threadIdx.x] =
            in[(size_t)(by + threadIdx.y + i) * C + bx + threadIdx.x];
    __syncthreads();
#pragma unroll
    for (int i = 0; i < 32; i += 8) {
        size_t idx = (size_t)(bx + threadIdx.y + i) * R + by + threadIdx.x;
        oh[idx] = __float2half_rn(tile[threadIdx.x][threadIdx.y + i]);
    }
}

// ---------------------------------------------------------------------------
// Fused middle (R7-best version): per (b,h,m) 32-token block linear attention.
// Epilogue writes attn as split fp16 hi/lo (GEMM2 operand format).
// ---------------------------------------------------------------------------
#define SQF_STRIDE 129
#define MID_SMEM_FLOATS (14336 + 2 * (32 * SQF_STRIDE) + 128 + 32)
#define MID_SMEM_BYTES  (MID_SMEM_FLOATS * 4)

__global__ __launch_bounds__(256)
void middle_kernel(const float* __restrict__ qkv, const float* __restrict__ proj,
                   __half* __restrict__ attn_h, __half* __restrict__ attn_l)
{
    extern __shared__ float sm[];
    float* sq    = sm;
    float* sk    = sm + 2048;
    float* sv    = sm + 4096;
    float* sp    = sm + 6144;
    float* skv   = sp;
    float* sqf   = sm + 14336;
    float* skf   = sqf + 32 * SQF_STRIDE;
    float* sksum = skf + 32 * SQF_STRIDE;
    float* sz    = sksum + 128;

    const int t = threadIdx.x;
    const int gb = blockIdx.x;
    const int b = gb / (HEADS * NBLK);
    const int rem = gb - b * (HEADS * NBLK);
    const int h = rem / NBLK;
    const int m = rem - h * NBLK;

    const float* base = qkv + ((size_t)(b * SEQ + m * BLK)) * (3 * DIM) + h * HEAD_DIM;
    for (int v4 = t; v4 < 512; v4 += 256) {
        int s = v4 >> 4, c = v4 & 15;
        const float* r = base + (size_t)s * (3 * DIM) + c * 4;
        ((float4*)sq)[v4] = *(const float4*)(r);
        ((float4*)sk)[v4] = *(const float4*)(r + DIM);
        ((float4*)sv)[v4] = *(const float4*)(r + 2 * DIM);
    }
    const float* ph = proj + (size_t)h * HEAD_DIM * FEAT;
    for (int v4 = t; v4 < 2048; v4 += 256)
        ((float4*)sp)[v4] = ((const float4*)ph)[v4];
    __syncthreads();

    {
        const int tS = t >> 5;
        const int tF = t & 31;
        float qa[4][4], ka[4][4];
#pragma unroll
        for (int i = 0; i < 4; i++)
#pragma unroll
            for (int j = 0; j < 4; j++) { qa[i][j] = 0.0f; ka[i][j] = 0.0f; }

        for (int d = 0; d < HEAD_DIM; d++) {
            float qv[4], kv_[4], pv[4];
#pragma unroll
            for (int i = 0; i < 4; i++) {
                qv[i]  = sq[(tS + 8 * i) * 64 + d];
                kv_[i] = sk[(tS + 8 * i) * 64 + d];
            }
#pragma unroll
            for (int j = 0; j < 4; j++)
                pv[j] = sp[d * 128 + tF + 32 * j];
#pragma unroll
            for (int i = 0; i < 4; i++)
#pragma unroll
                for (int j = 0; j < 4; j++) {
                    qa[i][j] += qv[i] * pv[j];
                    ka[i][j] += kv_[i] * pv[j];
                }
        }
#pragma unroll
        for (int i = 0; i < 4; i++) {
            int s = tS + 8 * i;
#pragma unroll
            for (int j = 0; j < 4; j++) {
                int f = tF + 32 * j;
                float x = qa[i][j];
                sqf[s * SQF_STRIDE + f] = (x > 0.0f) ? (x + 1.0f) : __expf(x);
                x = ka[i][j];
                skf[s * SQF_STRIDE + f] = (x > 0.0f) ? (x + 1.0f) : __expf(x);
            }
        }
    }
    __syncthreads();

    {
        const int tF = t >> 3;
        const int tD = t & 7;
        float kva[4][8];
#pragma unroll
        for (int j = 0; j < 4; j++)
#pragma unroll
            for (int i = 0; i < 8; i++) kva[j][i] = 0.0f;

        for (int s = 0; s < BLK; s++) {
            float kfv[4], vv[8];
#pragma unroll
            for (int j = 0; j < 4; j++) kfv[j] = skf[s * SQF_STRIDE + tF + 32 * j];
#pragma unroll
            for (int i = 0; i < 8; i++) vv[i] = sv[s * 64 + tD + 8 * i];
#pragma unroll
            for (int j = 0; j < 4; j++)
#pragma unroll
                for (int i = 0; i < 8; i++)
                    kva[j][i] += kfv[j] * vv[i];
        }
        if (t < FEAT) {
            float acc = 0.0f;
            for (int s = 0; s < BLK; s++) acc += skf[s * SQF_STRIDE + t];
            sksum[t] = acc;
        }
#pragma unroll
        for (int j = 0; j < 4; j++)
#pragma unroll
            for (int i = 0; i < 8; i++)
                skv[(tF + 32 * j) * 64 + tD + 8 * i] = kva[j][i];
    }
    __syncthreads();

    if (t < BLK) {
        float acc = 0.0f;
        for (int f = 0; f < FEAT; f++) acc += sqf[t * SQF_STRIDE + f] * sksum[f];
        sz[t] = 1.0f / (acc + 1e-8f);
    }
    __syncthreads();

    {
        const int tS = t >> 5;
        const int lane = t & 31;
        float oa[4][2];
#pragma unroll
        for (int i = 0; i < 4; i++) { oa[i][0] = 0.0f; oa[i][1] = 0.0f; }

        for (int f = 0; f < FEAT; f++) {
            float qv[4], kvv[2];
#pragma unroll
            for (int i = 0; i < 4; i++) qv[i] = sqf[(tS + 8 * i) * SQF_STRIDE + f];
            kvv[0] = skv[f * 64 + lane];
            kvv[1] = skv[f * 64 + lane + 32];
#pragma unroll
            for (int i = 0; i < 4; i++) {
                oa[i][0] += qv[i] * kvv[0];
                oa[i][1] += qv[i] * kvv[1];
            }
        }
        const int rowbase = b * SEQ + m * BLK;
#pragma unroll
        for (int i = 0; i < 4; i++) {
            int s = tS + 8 * i;
            float zz = sz[s];
            size_t off = (size_t)(rowbase + s) * DIM + h * HEAD_DIM;
            float v0 = oa[i][0] * zz;
            float v1 = oa[i][1] * zz;
            __half h0, l0, h1, l1;
            f16_split(v0, h0, l0);
            f16_split(v1, h1, l1);
            attn_h[off + lane]      = h0;
            attn_l[off + lane]      = l0;
            attn_h[off + lane + 32] = h1;
            attn_l[off + lane + 32] = l1;
        }
    }
}

// ---------------------------------------------------------------------------
extern "C" void kernel_launch(void* const* d_in, const int* in_sizes, int n_in,
                              void* d_out, int out_size)
{
    const float* x    = (const float*)d_in[0];
    const float* Wqkv = (const float*)d_in[1];
    const float* proj = (const float*)d_in[2];
    const float* Wout = (const float*)d_in[3];
    const float* bout = (const float*)d_in[4];
    float* out = (float*)d_out;

    float*  qkv; cudaGetSymbolAddress((void**)&qkv, g_qkv);
    __half *xh, *xl, *ah, *al, *wqh, *woh;
    cudaGetSymbolAddress((void**)&xh,  g_xh);
    cudaGetSymbolAddress((void**)&xl,  g_xl);
    cudaGetSymbolAddress((void**)&ah,  g_ah);
    cudaGetSymbolAddress((void**)&al,  g_al);
    cudaGetSymbolAddress((void**)&wqh, g_wqh);
    cudaGetSymbolAddress((void**)&woh, g_woh);

    cudaFuncSetAttribute(middle_kernel, cudaFuncAttributeMaxDynamicSharedMemorySize,
                         MID_SMEM_BYTES);
    cudaFuncSetAttribute(hgemm<false>, cudaFuncAttributeMaxDynamicSharedMemorySize,
                         G_SMEM);
    cudaFuncSetAttribute(hgemm<true>, cudaFuncAttributeMaxDynamicSharedMemorySize,
                         G_SMEM);

    // 0) operand prep: split x; transpose+round weights to fp16 hi
    {
        int n4 = ROWS * DIM / 4;
        split_kernel<<<(n4 + 255) / 256, 256>>>(x, xh, xl, n4);
    }
    transpose_h<<<dim3((3 * DIM) / 32, DIM / 32), dim3(32, 8)>>>(Wqkv, wqh, DIM, 3 * DIM);
    transpose_h<<<dim3(DIM / 32, DIM / 32), dim3(32, 8)>>>(Wout, woh, DIM, DIM);

    // 1) qkv = x @ Wqkv  (fp16x2 mma.sync: AhBh + AlBh)
    hgemm<false><<<dim3((3 * DIM) / BN, ROWS / BM), 256, G_SMEM>>>(
        xh, xl, wqh, nullptr, qkv, ROWS, 3 * DIM, DIM);

    // 2) fused per-block linear attention (writes split fp16 attn)
    middle_kernel<<<BATCH * HEADS * NBLK, 256, MID_SMEM_BYTES>>>(qkv, proj, ah, al);

    // 3) out = attn @ Wout + bout  (fp16x2 mma.sync)
    hgemm<true><<<dim3(DIM / BN, ROWS / BM), 256, G_SMEM>>>(
        ah, al, woh, bout, out, ROWS, DIM, DIM);
}

// round 11
// speedup vs baseline: 1.7643x; 1.4052x over previous
#include <cuda_runtime.h>
#include <cuda_fp16.h>
#include <cstdint>
#include <cstddef>

#define DIM      1024
#define HEADS    16
#define HEAD_DIM 64
#define BLK      32
#define FEAT     128
#define BATCH    4
#define SEQ      4096
#define NBLK     (SEQ / BLK)      // 128
#define ROWS     (BATCH * SEQ)    // 16384

// Scratch (allocation-free rule: __device__ globals)
__device__ float  g_qkv[(size_t)ROWS * 3 * DIM];     // 192 MB fp32
__device__ __half g_xh[(size_t)ROWS * DIM];
__device__ __half g_ah[(size_t)ROWS * DIM];
__device__ __half g_wqh[(size_t)3 * DIM * DIM];
__device__ __half g_woh[(size_t)DIM * DIM];

// ---------------------------------------------------------------------------
// helpers
// ---------------------------------------------------------------------------
__device__ __forceinline__ uint32_t smem_u32(const void* p) {
    uint32_t a;
    asm("{ .reg .u64 t; cvta.to.shared.u64 t, %1; cvt.u32.u64 %0, t; }" : "=r"(a) : "l"(p));
    return a;
}

#define SW128(off) ((off) ^ (((off) >> 3) & 0x70))

#define CP16(dst, src) \
    asm volatile("cp.async.cg.shared.global [%0], [%1], 16;" :: "r"(dst), "l"(src) : "memory")
#define CP_COMMIT() asm volatile("cp.async.commit_group;" ::: "memory")
#define CP_WAIT1()  asm volatile("cp.async.wait_group 1;" ::: "memory")

#define LDSM4(r0, r1, r2, r3, addr)                                           \
    asm volatile("ldmatrix.sync.aligned.m8n8.x4.shared.b16 {%0,%1,%2,%3}, [%4];" \
                 : "=r"(r0), "=r"(r1), "=r"(r2), "=r"(r3) : "r"(addr))

#define MMA_F16(d, a0, a1, a2, a3, b0, b1)                                    \
    asm volatile("mma.sync.aligned.m16n8k16.row.col.f32.f16.f16.f32 "         \
                 "{%0,%1,%2,%3}, {%4,%5,%6,%7}, {%8,%9}, {%0,%1,%2,%3};"      \
                 : "+f"((d)[0]), "+f"((d)[1]), "+f"((d)[2]), "+f"((d)[3])     \
                 : "r"(a0), "r"(a1), "r"(a2), "r"(a3), "r"(b0), "r"(b1))

// ---------------------------------------------------------------------------
// fp16 mma.sync GEMM: C = Ah @ Bh^T (+bias); both operands round-to-nearest
// fp16 (unbiased rounding; fp32 accumulate). CTA 128x128, BK=64 (128B rows,
// SW128), 8 warps (4Mx2N), 3-stage cp.async, 96KB smem -> 2 CTAs/SM,
// single sync/iter. 16 MMAs per k-step.
// ---------------------------------------------------------------------------
#define BM 128
#define BN 128
#define BKH 64
#define NSTAGE 3
#define TILE_B (BM * 128)          // 16384 B per operand tile
#define ST_BYTES (2 * TILE_B)      // 32768 B (Ah, Bh)
#define G_SMEM (NSTAGE * ST_BYTES) // 98304 B

template<bool BIAS>
__global__ __launch_bounds__(256, 2)
void hgemm(const __half* __restrict__ Ah, const __half* __restrict__ Bh,
           const float* __restrict__ bias, float* __restrict__ C,
           int M, int N, int K)
{
    extern __shared__ char smem[];
    const uint32_t sbase = smem_u32(smem);
    const int t = threadIdx.x;
    const int lid = t & 31, wid = t >> 5;
    const int wm = wid & 3, wn = wid >> 2;
    const int m0 = wm * 32, n0 = wn * 64;
    const int bn = blockIdx.x, bm = blockIdx.y;
    const int NK = K / BKH;

    const __half* Ahb = Ah + (size_t)bm * BM * K;
    const __half* Bhb = Bh + (size_t)bn * BN * K;

    const int prow = t >> 3;
    const int pch  = t & 7;

    auto load_stage = [&](int s, int kc) {
        const uint32_t sb0 = sbase + s * ST_BYTES;
        const int koff = kc * BKH;
#pragma unroll
        for (int i = 0; i < 4; i++) {
            int row = prow + i * 32;
            uint32_t off = SW128((uint32_t)(row * 128 + pch * 16));
            size_t g = (size_t)row * K + koff + pch * 8;
            CP16(sb0 + off,          Ahb + g);
            CP16(sb0 + TILE_B + off, Bhb + g);
        }
        CP_COMMIT();
    };

    const int lr = lid & 15;
    const int lk16 = (lid >> 4) * 16;
    const uint32_t aoff = (uint32_t)((m0 + lr) * 128 + lk16);
    uint32_t boff[4];
#pragma unroll
    for (int j = 0; j < 4; j++)
        boff[j] = (uint32_t)((n0 + 16 * j + lr) * 128 + lk16);

    float acc[2][8][4];
#pragma unroll
    for (int mi = 0; mi < 2; mi++)
#pragma unroll
        for (int f = 0; f < 8; f++)
#pragma unroll
            for (int r = 0; r < 4; r++) acc[mi][f][r] = 0.0f;

    load_stage(0, 0);
    load_stage(1, 1);

    for (int it = 0; it < NK; it++) {
        CP_WAIT1();
        __syncthreads();
        const int nxt = it + 2;
        if (nxt < NK) load_stage(nxt % NSTAGE, nxt);

        const uint32_t s0 = sbase + (it % NSTAGE) * ST_BYTES;
        const uint32_t sAh = s0;
        const uint32_t sBh = s0 + TILE_B;

#pragma unroll
        for (int ks = 0; ks < 4; ks++) {
            const uint32_t kb = ks * 32;
            uint32_t ah0[4], ah1[4];
            {
                uint32_t o0 = SW128(aoff + kb);
                uint32_t o1 = SW128(aoff + 16 * 128 + kb);
                LDSM4(ah0[0], ah0[1], ah0[2], ah0[3], sAh + o0);
                LDSM4(ah1[0], ah1[1], ah1[2], ah1[3], sAh + o1);
            }
#pragma unroll
            for (int j = 0; j < 4; j++) {
                uint32_t bh[4];
                uint32_t ob = SW128(boff[j] + kb);
                LDSM4(bh[0], bh[1], bh[2], bh[3], sBh + ob);

                MMA_F16(acc[0][2 * j + 0], ah0[0], ah0[1], ah0[2], ah0[3], bh[0], bh[2]);
                MMA_F16(acc[0][2 * j + 1], ah0[0], ah0[1], ah0[2], ah0[3], bh[1], bh[3]);
                MMA_F16(acc[1][2 * j + 0], ah1[0], ah1[1], ah1[2], ah1[3], bh[0], bh[2]);
                MMA_F16(acc[1][2 * j + 1], ah1[0], ah1[1], ah1[2], ah1[3], bh[1], bh[3]);
            }
        }
    }

    const int g = lid >> 2, tq = lid & 3;
#pragma unroll
    for (int mi = 0; mi < 2; mi++) {
        int rowl = m0 + mi * 16 + g;
#pragma unroll
        for (int f = 0; f < 8; f++) {
            int col = n0 + f * 8 + tq * 2;
            float b0 = 0.0f, b1 = 0.0f;
            if (BIAS) { b0 = bias[bn * BN + col]; b1 = bias[bn * BN + col + 1]; }
            float* p0 = C + (size_t)(bm * BM + rowl) * N + bn * BN + col;
            float* p1 = C + (size_t)(bm * BM + rowl + 8) * N + bn * BN + col;
            float2 v0 = { acc[mi][f][0] + b0, acc[mi][f][1] + b1 };
            float2 v1 = { acc[mi][f][2] + b0, acc[mi][f][3] + b1 };
            *(float2*)p0 = v0;
            *(float2*)p1 = v1;
        }
    }
}

// ---------------------------------------------------------------------------
// Round fp32 -> fp16 (rn), elementwise (float4 vectorized).
// ---------------------------------------------------------------------------
__global__ void round_kernel(const float* __restrict__ in, __half* __restrict__ h,
                             int n4)
{
    int i = blockIdx.x * blockDim.x + threadIdx.x;
    if (i >= n4) return;
    float4 v = ((const float4*)in)[i];
    ((__half2*)h)[2 * i]     = __halves2half2(__float2half_rn(v.x), __float2half_rn(v.y));
    ((__half2*)h)[2 * i + 1] = __halves2half2(__float2half_rn(v.z), __float2half_rn(v.w));
}

// ---------------------------------------------------------------------------
// Transpose + round: in fp32 [R,C] -> out fp16 [C,R] (rn). block (32,8).
// ---------------------------------------------------------------------------
__global__ void transpose_h(const float* __restrict__ in,
                            __half* __restrict__ oh, int R, int C)
{
    __shared__ float tile[32][33];
    int bx = blockIdx.x * 32, by = blockIdx.y * 32;
#pragma unroll
    for (int i = 0; i < 32; i += 8)
        tile[threadIdx.y + i][threadIdx.x] =
            in[(size_t)(by + threadIdx.y + i) * C + bx + threadIdx.x];
    __syncthreads();
#pragma unroll
    for (int i = 0; i < 32; i += 8) {
        size_t idx = (size_t)(bx + threadIdx.y + i) * R + by + threadIdx.x;
        oh[idx] = __float2half_rn(tile[threadIdx.x][threadIdx.y + i]);
    }
}

// ---------------------------------------------------------------------------
// Fused middle (R7-best version): per (b,h,m) 32-token block linear attention.
// Epilogue writes attn as fp16 rn (GEMM2 operand format).
// ---------------------------------------------------------------------------
#define SQF_STRIDE 129
#define MID_SMEM_FLOATS (14336 + 2 * (32 * SQF_STRIDE) + 128 + 32)
#define MID_SMEM_BYTES  (MID_SMEM_FLOATS * 4)

__global__ __launch_bounds__(256)
void middle_kernel(const float* __restrict__ qkv, const float* __restrict__ proj,
                   __half* __restrict__ attn_h)
{
    extern __shared__ float sm[];
    float* sq    = sm;
    float* sk    = sm + 2048;
    float* sv    = sm + 4096;
    float* sp    = sm + 6144;
    float* skv   = sp;
    float* sqf   = sm + 14336;
    float* skf   = sqf + 32 * SQF_STRIDE;
    float* sksum = skf + 32 * SQF_STRIDE;
    float* sz    = sksum + 128;

    const int t = threadIdx.x;
    const int gb = blockIdx.x;
    const int b = gb / (HEADS * NBLK);
    const int rem = gb - b * (HEADS * NBLK);
    const int h = rem / NBLK;
    const int m = rem - h * NBLK;

    const float* base = qkv + ((size_t)(b * SEQ + m * BLK)) * (3 * DIM) + h * HEAD_DIM;
    for (int v4 = t; v4 < 512; v4 += 256) {
        int s = v4 >> 4, c = v4 & 15;
        const float* r = base + (size_t)s * (3 * DIM) + c * 4;
        ((float4*)sq)[v4] = *(const float4*)(r);
        ((float4*)sk)[v4] = *(const float4*)(r + DIM);
        ((float4*)sv)[v4] = *(const float4*)(r + 2 * DIM);
    }
    const float* ph = proj + (size_t)h * HEAD_DIM * FEAT;
    for (int v4 = t; v4 < 2048; v4 += 256)
        ((float4*)sp)[v4] = ((const float4*)ph)[v4];
    __syncthreads();

    {
        const int tS = t >> 5;
        const int tF = t & 31;
        float qa[4][4], ka[4][4];
#pragma unroll
        for (int i = 0; i < 4; i++)
#pragma unroll
            for (int j = 0; j < 4; j++) { qa[i][j] = 0.0f; ka[i][j] = 0.0f; }

        for (int d = 0; d < HEAD_DIM; d++) {
            float qv[4], kv_[4], pv[4];
#pragma unroll
            for (int i = 0; i < 4; i++) {
                qv[i]  = sq[(tS + 8 * i) * 64 + d];
                kv_[i] = sk[(tS + 8 * i) * 64 + d];
            }
#pragma unroll
            for (int j = 0; j < 4; j++)
                pv[j] = sp[d * 128 + tF + 32 * j];
#pragma unroll
            for (int i = 0; i < 4; i++)
#pragma unroll
                for (int j = 0; j < 4; j++) {
                    qa[i][j] += qv[i] * pv[j];
                    ka[i][j] += kv_[i] * pv[j];
                }
        }
#pragma unroll
        for (int i = 0; i < 4; i++) {
            int s = tS + 8 * i;
#pragma unroll
            for (int j = 0; j < 4; j++) {
                int f = tF + 32 * j;
                float x = qa[i][j];
                sqf[s * SQF_STRIDE + f] = (x > 0.0f) ? (x + 1.0f) : __expf(x);
                x = ka[i][j];
                skf[s * SQF_STRIDE + f] = (x > 0.0f) ? (x + 1.0f) : __expf(x);
            }
        }
    }
    __syncthreads();

    {
        const int tF = t >> 3;
        const int tD = t & 7;
        float kva[4][8];
#pragma unroll
        for (int j = 0; j < 4; j++)
#pragma unroll
            for (int i = 0; i < 8; i++) kva[j][i] = 0.0f;

        for (int s = 0; s < BLK; s++) {
            float kfv[4], vv[8];
#pragma unroll
            for (int j = 0; j < 4; j++) kfv[j] = skf[s * SQF_STRIDE + tF + 32 * j];
#pragma unroll
            for (int i = 0; i < 8; i++) vv[i] = sv[s * 64 + tD + 8 * i];
#pragma unroll
            for (int j = 0; j < 4; j++)
#pragma unroll
                for (int i = 0; i < 8; i++)
                    kva[j][i] += kfv[j] * vv[i];
        }
        if (t < FEAT) {
            float acc = 0.0f;
            for (int s = 0; s < BLK; s++) acc += skf[s * SQF_STRIDE + t];
            sksum[t] = acc;
        }
#pragma unroll
        for (int j = 0; j < 4; j++)
#pragma unroll
            for (int i = 0; i < 8; i++)
                skv[(tF + 32 * j) * 64 + tD + 8 * i] = kva[j][i];
    }
    __syncthreads();

    if (t < BLK) {
        float acc = 0.0f;
        for (int f = 0; f < FEAT; f++) acc += sqf[t * SQF_STRIDE + f] * sksum[f];
        sz[t] = 1.0f / (acc + 1e-8f);
    }
    __syncthreads();

    {
        const int tS = t >> 5;
        const int lane = t & 31;
        float oa[4][2];
#pragma unroll
        for (int i = 0; i < 4; i++) { oa[i][0] = 0.0f; oa[i][1] = 0.0f; }

        for (int f = 0; f < FEAT; f++) {
            float qv[4], kvv[2];
#pragma unroll
            for (int i = 0; i < 4; i++) qv[i] = sqf[(tS + 8 * i) * SQF_STRIDE + f];
            kvv[0] = skv[f * 64 + lane];
            kvv[1] = skv[f * 64 + lane + 32];
#pragma unroll
            for (int i = 0; i < 4; i++) {
                oa[i][0] += qv[i] * kvv[0];
                oa[i][1] += qv[i] * kvv[1];
            }
        }
        const int rowbase = b * SEQ + m * BLK;
#pragma unroll
        for (int i = 0; i < 4; i++) {
            int s = tS + 8 * i;
            float zz = sz[s];
            size_t off = (size_t)(rowbase + s) * DIM + h * HEAD_DIM;
            attn_h[off + lane]      = __float2half_rn(oa[i][0] * zz);
            attn_h[off + lane + 32] = __float2half_rn(oa[i][1] * zz);
        }
    }
}

// ---------------------------------------------------------------------------
extern "C" void kernel_launch(void* const* d_in, const int* in_sizes, int n_in,
                              void* d_out, int out_size)
{
    const float* x    = (const float*)d_in[0];
    const float* Wqkv = (const float*)d_in[1];
    const float* proj = (const float*)d_in[2];
    const float* Wout = (const float*)d_in[3];
    const float* bout = (const float*)d_in[4];
    float* out = (float*)d_out;

    float*  qkv; cudaGetSymbolAddress((void**)&qkv, g_qkv);
    __half *xh, *ah, *wqh, *woh;
    cudaGetSymbolAddress((void**)&xh,  g_xh);
    cudaGetSymbolAddress((void**)&ah,  g_ah);
    cudaGetSymbolAddress((void**)&wqh, g_wqh);
    cudaGetSymbolAddress((void**)&woh, g_woh);

    cudaFuncSetAttribute(middle_kernel, cudaFuncAttributeMaxDynamicSharedMemorySize,
                         MID_SMEM_BYTES);
    cudaFuncSetAttribute(hgemm<false>, cudaFuncAttributeMaxDynamicSharedMemorySize,
                         G_SMEM);
    cudaFuncSetAttribute(hgemm<true>, cudaFuncAttributeMaxDynamicSharedMemorySize,
                         G_SMEM);

    // 0) operand prep: round x; transpose+round weights
    {
        int n4 = ROWS * DIM / 4;
        round_kernel<<<(n4 + 255) / 256, 256>>>(x, xh, n4);
    }
    transpose_h<<<dim3((3 * DIM) / 32, DIM / 32), dim3(32, 8)>>>(Wqkv, wqh, DIM, 3 * DIM);
    transpose_h<<<dim3(DIM / 32, DIM / 32), dim3(32, 8)>>>(Wout, woh, DIM, DIM);

    // 1) qkv = x @ Wqkv  (fp16 mma.sync, fp32 accumulate)
    hgemm<false><<<dim3((3 * DIM) / BN, ROWS / BM), 256, G_SMEM>>>(
        xh, wqh, nullptr, qkv, ROWS, 3 * DIM, DIM);

    // 2) fused per-block linear attention (writes fp16 attn)
    middle_kernel<<<BATCH * HEADS * NBLK, 256, MID_SMEM_BYTES>>>(qkv, proj, ah);

    // 3) out = attn @ Wout + bout  (fp16 mma.sync)
    hgemm<true><<<dim3(DIM / BN, ROWS / BM), 256, G_SMEM>>>(
        ah, woh, bout, out, ROWS, DIM, DIM);
}